// round 14
// baseline (speedup 1.0000x reference)
#include <cuda_runtime.h>
#include <cuda_fp16.h>
#include <cstdint>
#include <cstddef>

#define NT 2048
#define RST 144

// ---- smem layout (bytes) ----
#define BUF0   0          // h1 slot 0: [64][72] half
#define BUF1   9216       // h1 slot 1
#define A2H    18432      // h2 state
#define B1H    27648      // B tiles (fp16): 208*144 = 29952 each
#define B2AH   57600
#define B2BH   87552
#define O_WL   117504
#define O_PART 117760     // [64][8] float
#define SMEM_TOTAL 120832

__device__ __forceinline__ uint32_t s2u(const void* p){
    uint32_t a;
    asm("{ .reg .u64 t; cvta.to.shared.u64 t, %1; cvt.u32.u64 %0, t; }" : "=r"(a) : "l"(p));
    return a;
}
__device__ __forceinline__ void ldsm4(uint32_t* r, uint32_t a){
    asm volatile("ldmatrix.sync.aligned.m8n8.x4.shared.b16 {%0,%1,%2,%3}, [%4];"
        : "=r"(r[0]),"=r"(r[1]),"=r"(r[2]),"=r"(r[3]) : "r"(a));
}
__device__ __forceinline__ void mma16816(float* c, const uint32_t* a, uint32_t b0, uint32_t b1){
    asm volatile("mma.sync.aligned.m16n8k16.row.col.f32.f16.f16.f32 "
        "{%0,%1,%2,%3}, {%4,%5,%6,%7}, {%8,%9}, {%0,%1,%2,%3};"
        : "+f"(c[0]),"+f"(c[1]),"+f"(c[2]),"+f"(c[3])
        : "r"(a[0]),"r"(a[1]),"r"(a[2]),"r"(a[3]), "r"(b0),"r"(b1));
}
__device__ __forceinline__ void nbar_sync(int id, int cnt){
    asm volatile("bar.sync %0, %1;" :: "r"(id), "r"(cnt) : "memory");
}
__device__ __forceinline__ void nbar_arrive(int id, int cnt){
    asm volatile("bar.arrive %0, %1;" :: "r"(id), "r"(cnt) : "memory");
}
// ---- packed f16x2 helpers ----
__device__ __forceinline__ uint32_t pkf2(float a, float b){   // lo=a, hi=b
    uint32_t r;
    asm("{ .reg .b16 l, h; cvt.rn.f16.f32 l, %1; cvt.rn.f16.f32 h, %2; mov.b32 %0, {l, h}; }"
        : "=r"(r) : "f"(a), "f"(b));
    return r;
}
__device__ __forceinline__ void upkf2(uint32_t v, float& a, float& b){
    asm("{ .reg .b16 l, h; mov.b32 {l, h}, %2; cvt.f32.f16 %0, l; cvt.f32.f16 %1, h; }"
        : "=f"(a), "=f"(b) : "r"(v));
}
__device__ __forceinline__ uint32_t tanh2p(uint32_t x){        // MUFU.TANH f16x2: 2 tanhs, 1 op
    uint32_t r; asm("tanh.approx.f16x2 %0, %1;" : "=r"(r) : "r"(x)); return r;
}
__device__ __forceinline__ uint32_t mulh2(uint32_t a, uint32_t b){
    uint32_t r; asm("mul.rn.f16x2 %0, %1, %2;" : "=r"(r) : "r"(a), "r"(b)); return r;
}
__device__ __forceinline__ uint32_t fmah2(uint32_t a, uint32_t b, uint32_t c){
    uint32_t r; asm("fma.rn.f16x2 %0, %1, %2, %3;" : "=r"(r) : "r"(a), "r"(b), "r"(c)); return r;
}
// packed tile-pair epilogue: gates ga(tile0)/gb(tile1) -> updates c0,c1, returns f16x2 {h0,h1}
__device__ __forceinline__ uint32_t epi2(const float* ga, const float* gb,
                                         float& c0, float& c1, int p){
    const uint32_t H05 = 0x38003800u;   // (0.5, 0.5)
    uint32_t pg0 = pkf2(ga[0], gb[0]);
    uint32_t pg1 = pkf2(ga[1], gb[1]);
    uint32_t pg2 = pkf2(ga[2], gb[2]);
    uint32_t pg3 = pkf2(ga[3], gb[3]);
    uint32_t r0 = __shfl_xor_sync(0xFFFFFFFFu, pg0, 1);
    uint32_t r1 = __shfl_xor_sync(0xFFFFFFFFu, pg1, 1);
    uint32_t r2 = __shfl_xor_sync(0xFFFFFFFFu, pg2, 1);
    uint32_t r3 = __shfl_xor_sync(0xFFFFFFFFu, pg3, 1);
    uint32_t gi = p ? r2 : pg0;
    uint32_t gf = p ? r3 : pg1;
    uint32_t gG = p ? pg2 : r0;
    uint32_t gO = p ? pg3 : r1;
    uint32_t ti = tanh2p(mulh2(gi, H05));    // sig(x) = 0.5*tanh(0.5x)+0.5
    uint32_t tf = tanh2p(mulh2(gf, H05));
    uint32_t tg = tanh2p(gG);
    uint32_t to = tanh2p(mulh2(gO, H05));
    float ti0,ti1,tf0,tf1,tg0,tg1;
    upkf2(ti, ti0, ti1); upkf2(tf, tf0, tf1); upkf2(tg, tg0, tg1);
    float cn0 = fmaf(fmaf(0.5f, tf0, 0.5f), c0, fmaf(0.5f, ti0, 0.5f) * tg0);
    float cn1 = fmaf(fmaf(0.5f, tf1, 0.5f), c1, fmaf(0.5f, ti1, 0.5f) * tg1);
    c0 = cn0; c1 = cn1;
    uint32_t so = fmah2(to, H05, H05);       // sig(gO) packed
    uint32_t tc = tanh2p(pkf2(cn0, cn1));    // tanh(cn) packed
    return mulh2(so, tc);                    // h packed f16x2
}
// stage [204-row] weight block into [208][72] fp16 tile; cols [0,51)=W, 51=wx, 52=bias
__device__ void stageB(const float* W, const float* wx, const float* ba, const float* bb,
                       half* hi, int tid){
    for (int i = tid; i < 208*72; i += 512){
        int n = i / 72, k = i - n*72;
        float v = 0.0f;
        if (n < 204){
            int u = n >> 2, g = n & 3, row = g*51 + u;
            if (k < 51)                 v = W[row*51 + k];
            else if (k == 51 && wx)     v = wx[row];
            else if (k == 52 && ba)     v = ba[row] + bb[row];
        }
        hi[i] = __float2half(v);
    }
}

__global__ void __launch_bounds__(512, 1)
lstm_ws_kernel(const float* __restrict__ input,
               const float* __restrict__ Wih1, const float* __restrict__ Whh1,
               const float* __restrict__ bih1, const float* __restrict__ bhh1,
               const float* __restrict__ Wih2, const float* __restrict__ Whh2,
               const float* __restrict__ bih2, const float* __restrict__ bhh2,
               const float* __restrict__ Wlin, const float* __restrict__ blin,
               float* __restrict__ out)
{
    extern __shared__ char smem[];
    const int tid  = threadIdx.x;
    const int lane = tid & 31;
    const int wid  = tid >> 5;
    const int b0   = blockIdx.x * 64;
    const uint32_t sb = s2u(smem);

    half* buf[2] = { (half*)(smem + BUF0), (half*)(smem + BUF1) };
    half* a2h = (half*)(smem + A2H);

    // ---- init: stage weights, zero state ----
    stageB(Whh1, Wih1, bih1, bhh1, (half*)(smem + B1H),  tid);
    stageB(Wih2, 0,    bih2, bhh2, (half*)(smem + B2AH), tid);
    stageB(Whh2, 0,    0,    0,    (half*)(smem + B2BH), tid);
    for (int i = tid; i < 27648/4; i += 512) ((uint32_t*)(smem + BUF0))[i] = 0u;  // h1x2, h2
    for (int i = tid; i < 64*8; i += 512) ((float*)(smem + O_PART))[i] = 0.0f;
    if (tid < 52) ((float*)(smem + O_WL))[tid] = (tid < 51) ? Wlin[tid] : 0.0f;
    __syncthreads();
    if (tid < 64){
        buf[0][tid*72 + 51] = __float2half(input[(size_t)(b0 + tid)*NT]);  // x(0)
        buf[0][tid*72 + 52] = __float2half(1.0f);
        buf[1][tid*72 + 52] = __float2half(1.0f);
    }
    __syncthreads();

    const int g   = lane >> 2;
    const int tig = lane & 3;
    const int p   = tig & 1;
    const uint32_t aro  = (uint32_t)(((lane>>3)&1)*8*RST + (lane&7)*RST + ((lane>>4)&1)*16);
    const uint32_t bro4 = (uint32_t)((lane&7)*RST + ((lane>>3)&3)*16);
    const float* wlS = (const float*)(smem + O_WL);
    float* part = (float*)(smem + O_PART);

    if (wid < 6){
        // ================= X group: layer-1 recurrence (producer) =================
        const int mg = wid & 1, qx = wid >> 1;
        const int ns = qx * 9;
        const int nt = (qx == 2) ? 8 : 9;
        const int m0 = mg * 32;
        const int er0 = m0 + p*8 + g, er1 = er0 + 16;
        const uint32_t ab[2][2] = {
            { sb + BUF0 + m0*RST + aro, sb + BUF0 + m0*RST + aro + 16*RST },
            { sb + BUF1 + m0*RST + aro, sb + BUF1 + m0*RST + aro + 16*RST } };
        const uint32_t b1hb = sb + B1H + bro4;

        float c1[2][9];
        #pragma unroll
        for (int j = 0; j < 9; j++){ c1[0][j] = 0.0f; c1[1][j] = 0.0f; }

        uint32_t fa[2][16];
        #pragma unroll
        for (int kc = 0; kc < 4; kc++){
            ldsm4(&fa[0][kc*4], ab[0][0] + kc*32);
            ldsm4(&fa[1][kc*4], ab[0][1] + kc*32);
        }

        #pragma unroll 1
        for (int t = 0; t < NT; t++){
            const int s = t & 1;
            if (t >= 2) nbar_sync(3 + s, 512);            // wait slot s free
            float xv = 0.0f;
            if (tid < 64 && t + 1 < NT) xv = input[(size_t)(b0 + tid)*NT + t + 1];
            half* bh = buf[s];

            #pragma unroll
            for (int j = 0; j < 9; j++){
                if (j >= nt) break;
                const uint32_t nofs = (uint32_t)((ns + j)*8*RST);
                float g1a[4] = {0,0,0,0}, g1b[4] = {0,0,0,0};
                uint32_t b4[4];
                #pragma unroll
                for (int kc2 = 0; kc2 < 2; kc2++){
                    ldsm4(b4, b1hb + nofs + kc2*64);
                    mma16816(g1a, &fa[0][(2*kc2)*4],   b4[0], b4[1]);
                    mma16816(g1b, &fa[1][(2*kc2)*4],   b4[0], b4[1]);
                    mma16816(g1a, &fa[0][(2*kc2+1)*4], b4[2], b4[3]);
                    mma16816(g1b, &fa[1][(2*kc2+1)*4], b4[2], b4[3]);
                }
                uint32_t hp = epi2(g1a, g1b, c1[0][j], c1[1][j], p);
                int u = 2*(ns + j) + (tig >> 1);
                if (u < 51){
                    bh[er0*72 + u] = __ushort_as_half((unsigned short)(hp & 0xFFFFu));
                    bh[er1*72 + u] = __ushort_as_half((unsigned short)(hp >> 16));
                }
            }
            if (tid < 64 && t + 1 < NT) bh[tid*72 + 51] = __float2half(xv);
            __threadfence_block();
            nbar_sync(6, 192);                            // intra-X: buf[s] complete
            nbar_arrive(1 + s, 512);                      // signal full[s] to Y
            #pragma unroll
            for (int kc = 0; kc < 4; kc++){               // reload h1(t) for t+1
                ldsm4(&fa[0][kc*4], ab[s][0] + kc*32);
                ldsm4(&fa[1][kc*4], ab[s][1] + kc*32);
            }
        }
    } else {
        // ================= Y group: layer-2 + output (consumer) =================
        const int yw = wid - 6;
        const int mg = yw & 1, qy = yw >> 1;
        const int nt = (qy == 0) ? 6 : 5;
        const int ns = (qy == 0) ? 0 : 6 + 5*(qy - 1);
        const int m0 = mg * 32;
        const int er0 = m0 + p*8 + g, er1 = er0 + 16;
        const uint32_t ab[2][2] = {
            { sb + BUF0 + m0*RST + aro, sb + BUF0 + m0*RST + aro + 16*RST },
            { sb + BUF1 + m0*RST + aro, sb + BUF1 + m0*RST + aro + 16*RST } };
        const uint32_t a2b0 = sb + A2H + m0*RST + aro, a2b1 = a2b0 + 16*RST;
        const uint32_t bahb = sb + B2AH + bro4;
        const uint32_t bbhb = sb + B2BH + bro4;
        const float blin0 = blin[0];

        float c2[2][6], wlr[6];
        #pragma unroll
        for (int j = 0; j < 6; j++){
            c2[0][j] = 0.0f; c2[1][j] = 0.0f;
            wlr[j] = wlS[2*(ns + j) + (tig >> 1)];
        }
        uint32_t fa1[2][16], fa2[2][16];
        #pragma unroll
        for (int kc = 0; kc < 4; kc++){                   // h2(-1) = 0
            ldsm4(&fa2[0][kc*4], a2b0 + kc*32);
            ldsm4(&fa2[1][kc*4], a2b1 + kc*32);
        }

        #pragma unroll 1
        for (int t = 0; t < NT; t++){
            const int s = t & 1;
            nbar_sync(1 + s, 512);                        // wait full[s]: h1(t) ready
            #pragma unroll
            for (int kc = 0; kc < 4; kc++){
                ldsm4(&fa1[0][kc*4], ab[s][0] + kc*32);
                ldsm4(&fa1[1][kc*4], ab[s][1] + kc*32);
            }
            float pd0 = 0.0f, pd1 = 0.0f;
            #pragma unroll
            for (int j = 0; j < 6; j++){
                if (j >= nt) break;
                const uint32_t nofs = (uint32_t)((ns + j)*8*RST);
                float g2a[4] = {0,0,0,0}, g2b[4] = {0,0,0,0};
                uint32_t b4[4];
                #pragma unroll
                for (int kc2 = 0; kc2 < 2; kc2++){
                    ldsm4(b4, bahb + nofs + kc2*64);
                    mma16816(g2a, &fa1[0][(2*kc2)*4],   b4[0], b4[1]);
                    mma16816(g2b, &fa1[1][(2*kc2)*4],   b4[0], b4[1]);
                    mma16816(g2a, &fa1[0][(2*kc2+1)*4], b4[2], b4[3]);
                    mma16816(g2b, &fa1[1][(2*kc2+1)*4], b4[2], b4[3]);
                }
                #pragma unroll
                for (int kc2 = 0; kc2 < 2; kc2++){
                    ldsm4(b4, bbhb + nofs + kc2*64);
                    mma16816(g2a, &fa2[0][(2*kc2)*4],   b4[0], b4[1]);
                    mma16816(g2b, &fa2[1][(2*kc2)*4],   b4[0], b4[1]);
                    mma16816(g2a, &fa2[0][(2*kc2+1)*4], b4[2], b4[3]);
                    mma16816(g2b, &fa2[1][(2*kc2+1)*4], b4[2], b4[3]);
                }
                uint32_t hp = epi2(g2a, g2b, c2[0][j], c2[1][j], p);
                half hl = __ushort_as_half((unsigned short)(hp & 0xFFFFu));
                half hh = __ushort_as_half((unsigned short)(hp >> 16));
                int u = 2*(ns + j) + (tig >> 1);
                if (u < 51){
                    a2h[er0*72 + u] = hl;
                    a2h[er1*72 + u] = hh;
                }
                pd0 = fmaf(__half2float(hl), wlr[j], pd0);
                pd1 = fmaf(__half2float(hh), wlr[j], pd1);
            }
            pd0 += __shfl_xor_sync(0xFFFFFFFFu, pd0, 2);
            pd1 += __shfl_xor_sync(0xFFFFFFFFu, pd1, 2);
            if (tig < 2){
                part[er0*8 + qy] = pd0;
                part[er1*8 + qy] = pd1;
            }
            __threadfence_block();
            nbar_sync(5, 320);                            // intra-Y: a2h + part done
            if (tid >= 256 && tid < 320){
                const int ot = tid - 256;
                const float* pr = part + ot*8;
                out[(size_t)(b0 + ot)*NT + t] =
                    (pr[0] + pr[1]) + (pr[2] + pr[3]) + pr[4] + blin0;
            }
            #pragma unroll
            for (int kc = 0; kc < 4; kc++){               // reload h2(t) for t+1
                ldsm4(&fa2[0][kc*4], a2b0 + kc*32);
                ldsm4(&fa2[1][kc*4], a2b1 + kc*32);
            }
            nbar_sync(5, 320);                            // guard fa2 loads vs next writes
            if (t < NT - 2) nbar_arrive(3 + s, 512);      // release slot s to X
        }
    }
}

extern "C" void kernel_launch(void* const* d_in, const int* in_sizes, int n_in,
                              void* d_out, int out_size)
{
    (void)in_sizes; (void)n_in; (void)out_size;
    const float* input = (const float*)d_in[0];
    const float* Wih1  = (const float*)d_in[1];
    const float* Whh1  = (const float*)d_in[2];
    const float* bih1  = (const float*)d_in[3];
    const float* bhh1  = (const float*)d_in[4];
    const float* Wih2  = (const float*)d_in[5];
    const float* Whh2  = (const float*)d_in[6];
    const float* bih2  = (const float*)d_in[7];
    const float* bhh2  = (const float*)d_in[8];
    const float* Wlin  = (const float*)d_in[9];
    const float* blin  = (const float*)d_in[10];
    float* out = (float*)d_out;

    cudaFuncSetAttribute(lstm_ws_kernel, cudaFuncAttributeMaxDynamicSharedMemorySize, SMEM_TOTAL);
    lstm_ws_kernel<<<128, 512, SMEM_TOTAL>>>(input, Wih1, Whh1, bih1, bhh1,
                                             Wih2, Whh2, bih2, bhh2, Wlin, blin, out);
}

// round 15
// speedup vs baseline: 1.0668x; 1.0668x over previous
#include <cuda_runtime.h>
#include <cuda_fp16.h>
#include <cstdint>
#include <cstddef>

#define NT 2048
#define RST 144

// ---- smem layout (bytes) ----
#define BUF0   0          // h1 slot 0: [64][72] half (rows 0-31 coh0, 32-63 coh1)
#define BUF1   9216       // h1 slot 1
#define A2H    18432      // h2 state
#define B1H    27648      // B tiles (fp16): 208*144 = 29952 each (shared by both cohorts)
#define B2AH   57600
#define B2BH   87552
#define O_WL   117504
#define O_PART 117760     // [64][8] float
#define SMEM_TOTAL 120832

__device__ __forceinline__ uint32_t s2u(const void* p){
    uint32_t a;
    asm("{ .reg .u64 t; cvta.to.shared.u64 t, %1; cvt.u32.u64 %0, t; }" : "=r"(a) : "l"(p));
    return a;
}
__device__ __forceinline__ void ldsm4(uint32_t* r, uint32_t a){
    asm volatile("ldmatrix.sync.aligned.m8n8.x4.shared.b16 {%0,%1,%2,%3}, [%4];"
        : "=r"(r[0]),"=r"(r[1]),"=r"(r[2]),"=r"(r[3]) : "r"(a));
}
__device__ __forceinline__ void mma16816(float* c, const uint32_t* a, uint32_t b0, uint32_t b1){
    asm volatile("mma.sync.aligned.m16n8k16.row.col.f32.f16.f16.f32 "
        "{%0,%1,%2,%3}, {%4,%5,%6,%7}, {%8,%9}, {%0,%1,%2,%3};"
        : "+f"(c[0]),"+f"(c[1]),"+f"(c[2]),"+f"(c[3])
        : "r"(a[0]),"r"(a[1]),"r"(a[2]),"r"(a[3]), "r"(b0),"r"(b1));
}
__device__ __forceinline__ void nbar_sync(int id, int cnt){
    asm volatile("bar.sync %0, %1;" :: "r"(id), "r"(cnt) : "memory");
}
__device__ __forceinline__ void nbar_arrive(int id, int cnt){
    asm volatile("bar.arrive %0, %1;" :: "r"(id), "r"(cnt) : "memory");
}
// HW tanh unit: 1 MUFU op (plain PTX, sm_75+)
__device__ __forceinline__ float tanh_ap(float x){
    float r;
    asm("tanh.approx.f32 %0, %1;" : "=f"(r) : "f"(x));
    return r;
}
__device__ __forceinline__ float fast_sig(float x){
    return fmaf(0.5f, tanh_ap(0.5f * x), 0.5f);   // exact identity
}
__device__ __forceinline__ float fast_tanh(float x){
    return tanh_ap(x);
}
__device__ __forceinline__ float epi_update(const float* gc, float& c, int p){
    float r0 = __shfl_xor_sync(0xFFFFFFFFu, gc[0], 1);
    float r1 = __shfl_xor_sync(0xFFFFFFFFu, gc[1], 1);
    float r2 = __shfl_xor_sync(0xFFFFFFFFu, gc[2], 1);
    float r3 = __shfl_xor_sync(0xFFFFFFFFu, gc[3], 1);
    float gi = p ? r2 : gc[0];
    float gf = p ? r3 : gc[1];
    float gG = p ? gc[2] : r0;
    float gO = p ? gc[3] : r1;
    float cn = fast_sig(gf)*c + fast_sig(gi)*fast_tanh(gG);
    c = cn;
    return fast_sig(gO)*fast_tanh(cn);
}
// stage [204-row] weight block into [208][72] fp16 tile; cols [0,51)=W, 51=wx, 52=bias
__device__ void stageB(const float* W, const float* wx, const float* ba, const float* bb,
                       half* hi, int tid){
    for (int i = tid; i < 208*72; i += 512){
        int n = i / 72, k = i - n*72;
        float v = 0.0f;
        if (n < 204){
            int u = n >> 2, g = n & 3, row = g*51 + u;
            if (k < 51)                 v = W[row*51 + k];
            else if (k == 51 && wx)     v = wx[row];
            else if (k == 52 && ba)     v = ba[row] + bb[row];
        }
        hi[i] = __float2half(v);
    }
}

__global__ void __launch_bounds__(512, 1)
lstm_ws_kernel(const float* __restrict__ input,
               const float* __restrict__ Wih1, const float* __restrict__ Whh1,
               const float* __restrict__ bih1, const float* __restrict__ bhh1,
               const float* __restrict__ Wih2, const float* __restrict__ Whh2,
               const float* __restrict__ bih2, const float* __restrict__ bhh2,
               const float* __restrict__ Wlin, const float* __restrict__ blin,
               float* __restrict__ out)
{
    extern __shared__ char smem[];
    const int tid  = threadIdx.x;
    const int lane = tid & 31;
    const int wid  = tid >> 5;
    const int b0   = blockIdx.x * 64;
    const uint32_t sb = s2u(smem);

    half* buf[2] = { (half*)(smem + BUF0), (half*)(smem + BUF1) };
    half* a2h = (half*)(smem + A2H);

    // ---- init: stage weights, zero state ----
    stageB(Whh1, Wih1, bih1, bhh1, (half*)(smem + B1H),  tid);
    stageB(Wih2, 0,    bih2, bhh2, (half*)(smem + B2AH), tid);
    stageB(Whh2, 0,    0,    0,    (half*)(smem + B2BH), tid);
    for (int i = tid; i < 27648/4; i += 512) ((uint32_t*)(smem + BUF0))[i] = 0u;  // h1x2, h2
    for (int i = tid; i < 64*8; i += 512) ((float*)(smem + O_PART))[i] = 0.0f;
    if (tid < 52) ((float*)(smem + O_WL))[tid] = (tid < 51) ? Wlin[tid] : 0.0f;
    __syncthreads();
    if (tid < 64){
        buf[0][tid*72 + 51] = __float2half(input[(size_t)(b0 + tid)*NT]);  // x(0)
        buf[0][tid*72 + 52] = __float2half(1.0f);
        buf[1][tid*72 + 52] = __float2half(1.0f);
    }
    __syncthreads();

    // ---- cohort geometry: warps 0-7 -> cohort 0 (elems 0-31), 8-15 -> cohort 1 (32-63) ----
    const int coh = wid >> 3;
    const int cw  = wid & 7;           // warp within cohort: 0-2 = X, 3-7 = Y
    const int m0  = coh * 32;
    // named barriers: cohort0 uses 1..6, cohort1 uses 7..12
    const int B_FULL = 1 + coh*6;      // +s
    const int B_FREE = 3 + coh*6;      // +s
    const int B_IX   = 5 + coh*6;
    const int B_IY   = 6 + coh*6;

    const int g   = lane >> 2;
    const int tig = lane & 3;
    const int p   = tig & 1;
    const uint32_t aro  = (uint32_t)(((lane>>3)&1)*8*RST + (lane&7)*RST + ((lane>>4)&1)*16);
    const uint32_t bro4 = (uint32_t)((lane&7)*RST + ((lane>>3)&3)*16);
    const float* wlS = (const float*)(smem + O_WL);
    float* part = (float*)(smem + O_PART);

    const int er0 = m0 + p*8 + g, er1 = er0 + 16;
    const uint32_t ab[2][2] = {
        { sb + BUF0 + m0*RST + aro, sb + BUF0 + m0*RST + aro + 16*RST },
        { sb + BUF1 + m0*RST + aro, sb + BUF1 + m0*RST + aro + 16*RST } };

    if (cw < 3){
        // ================= X: layer-1 recurrence (3 warps per cohort) =================
        const int qx = cw;
        const int ns = qx * 9;
        const int nt = (qx == 2) ? 8 : 9;
        const uint32_t b1hb = sb + B1H + bro4;
        const int xe = m0 + lane;          // elem this thread loads x for (cw==0 only)

        float c1[2][9];
        #pragma unroll
        for (int j = 0; j < 9; j++){ c1[0][j] = 0.0f; c1[1][j] = 0.0f; }

        uint32_t fa[2][16];
        #pragma unroll
        for (int kc = 0; kc < 4; kc++){
            ldsm4(&fa[0][kc*4], ab[0][0] + kc*32);
            ldsm4(&fa[1][kc*4], ab[0][1] + kc*32);
        }

        #pragma unroll 1
        for (int t = 0; t < NT; t++){
            const int s = t & 1;
            if (t >= 2) nbar_sync(B_FREE + s, 256);       // wait slot s free
            float xv = 0.0f;
            if (cw == 0 && t + 1 < NT) xv = input[(size_t)(b0 + xe)*NT + t + 1];
            half* bh = buf[s];

            #pragma unroll
            for (int j = 0; j < 9; j++){
                if (j >= nt) break;
                const uint32_t nofs = (uint32_t)((ns + j)*8*RST);
                float g1a[4] = {0,0,0,0}, g1b[4] = {0,0,0,0};
                uint32_t b4[4];
                #pragma unroll
                for (int kc2 = 0; kc2 < 2; kc2++){
                    ldsm4(b4, b1hb + nofs + kc2*64);
                    mma16816(g1a, &fa[0][(2*kc2)*4],   b4[0], b4[1]);
                    mma16816(g1b, &fa[1][(2*kc2)*4],   b4[0], b4[1]);
                    mma16816(g1a, &fa[0][(2*kc2+1)*4], b4[2], b4[3]);
                    mma16816(g1b, &fa[1][(2*kc2+1)*4], b4[2], b4[3]);
                }
                float h0 = epi_update(g1a, c1[0][j], p);
                float h1 = epi_update(g1b, c1[1][j], p);
                int u = 2*(ns + j) + (tig >> 1);
                if (u < 51){
                    bh[er0*72 + u] = __float2half(h0);
                    bh[er1*72 + u] = __float2half(h1);
                }
            }
            if (cw == 0 && t + 1 < NT) bh[xe*72 + 51] = __float2half(xv);
            __threadfence_block();
            nbar_sync(B_IX, 96);                          // intra-X: buf[s] rows done
            nbar_arrive(B_FULL + s, 256);                 // signal full[s] to Y
            #pragma unroll
            for (int kc = 0; kc < 4; kc++){               // reload h1(t) for t+1
                ldsm4(&fa[0][kc*4], ab[s][0] + kc*32);
                ldsm4(&fa[1][kc*4], ab[s][1] + kc*32);
            }
        }
    } else {
        // ================= Y: layer-2 + output (5 warps per cohort) =================
        const int qy = cw - 3;             // 0..4
        const int nt = (qy == 0) ? 6 : 5;
        const int ns = (qy == 0) ? 0 : 6 + 5*(qy - 1);
        const uint32_t a2b0 = sb + A2H + m0*RST + aro, a2b1 = a2b0 + 16*RST;
        const uint32_t bahb = sb + B2AH + bro4;
        const uint32_t bbhb = sb + B2BH + bro4;
        const float blin0 = blin[0];
        const int oe = m0 + lane;          // out elem (cw==3 only)

        float c2[2][6], wlr[6];
        #pragma unroll
        for (int j = 0; j < 6; j++){
            c2[0][j] = 0.0f; c2[1][j] = 0.0f;
            wlr[j] = wlS[2*(ns + j) + (tig >> 1)];
        }
        uint32_t fa1[2][16], fa2[2][16];
        #pragma unroll
        for (int kc = 0; kc < 4; kc++){                   // h2(-1) = 0
            ldsm4(&fa2[0][kc*4], a2b0 + kc*32);
            ldsm4(&fa2[1][kc*4], a2b1 + kc*32);
        }

        #pragma unroll 1
        for (int t = 0; t < NT; t++){
            const int s = t & 1;
            nbar_sync(B_FULL + s, 256);                   // wait full[s]: h1(t) ready
            #pragma unroll
            for (int kc = 0; kc < 4; kc++){
                ldsm4(&fa1[0][kc*4], ab[s][0] + kc*32);
                ldsm4(&fa1[1][kc*4], ab[s][1] + kc*32);
            }
            float pd0 = 0.0f, pd1 = 0.0f;
            #pragma unroll
            for (int j = 0; j < 6; j++){
                if (j >= nt) break;
                const uint32_t nofs = (uint32_t)((ns + j)*8*RST);
                float g2a[4] = {0,0,0,0}, g2b[4] = {0,0,0,0};
                uint32_t b4[4];
                #pragma unroll
                for (int kc2 = 0; kc2 < 2; kc2++){
                    ldsm4(b4, bahb + nofs + kc2*64);
                    mma16816(g2a, &fa1[0][(2*kc2)*4],   b4[0], b4[1]);
                    mma16816(g2b, &fa1[1][(2*kc2)*4],   b4[0], b4[1]);
                    mma16816(g2a, &fa1[0][(2*kc2+1)*4], b4[2], b4[3]);
                    mma16816(g2b, &fa1[1][(2*kc2+1)*4], b4[2], b4[3]);
                }
                #pragma unroll
                for (int kc2 = 0; kc2 < 2; kc2++){
                    ldsm4(b4, bbhb + nofs + kc2*64);
                    mma16816(g2a, &fa2[0][(2*kc2)*4],   b4[0], b4[1]);
                    mma16816(g2b, &fa2[1][(2*kc2)*4],   b4[0], b4[1]);
                    mma16816(g2a, &fa2[0][(2*kc2+1)*4], b4[2], b4[3]);
                    mma16816(g2b, &fa2[1][(2*kc2+1)*4], b4[2], b4[3]);
                }
                float h0 = epi_update(g2a, c2[0][j], p);
                float h1 = epi_update(g2b, c2[1][j], p);
                int u = 2*(ns + j) + (tig >> 1);
                if (u < 51){
                    a2h[er0*72 + u] = __float2half(h0);
                    a2h[er1*72 + u] = __float2half(h1);
                }
                pd0 = fmaf(h0, wlr[j], pd0);
                pd1 = fmaf(h1, wlr[j], pd1);
            }
            pd0 += __shfl_xor_sync(0xFFFFFFFFu, pd0, 2);
            pd1 += __shfl_xor_sync(0xFFFFFFFFu, pd1, 2);
            if (tig < 2){
                part[er0*8 + qy] = pd0;
                part[er1*8 + qy] = pd1;
            }
            __threadfence_block();
            nbar_sync(B_IY, 160);                         // intra-Y: a2h + part done
            if (cw == 3){
                const float* pr = part + oe*8;
                out[(size_t)(b0 + oe)*NT + t] =
                    (pr[0] + pr[1]) + (pr[2] + pr[3]) + pr[4] + blin0;
            }
            #pragma unroll
            for (int kc = 0; kc < 4; kc++){               // reload h2(t) for t+1
                ldsm4(&fa2[0][kc*4], a2b0 + kc*32);
                ldsm4(&fa2[1][kc*4], a2b1 + kc*32);
            }
            nbar_sync(B_IY, 160);                         // guard fa2 loads vs next writes
            if (t < NT - 2) nbar_arrive(B_FREE + s, 256); // release slot s to X
        }
    }
}

extern "C" void kernel_launch(void* const* d_in, const int* in_sizes, int n_in,
                              void* d_out, int out_size)
{
    (void)in_sizes; (void)n_in; (void)out_size;
    const float* input = (const float*)d_in[0];
    const float* Wih1  = (const float*)d_in[1];
    const float* Whh1  = (const float*)d_in[2];
    const float* bih1  = (const float*)d_in[3];
    const float* bhh1  = (const float*)d_in[4];
    const float* Wih2  = (const float*)d_in[5];
    const float* Whh2  = (const float*)d_in[6];
    const float* bih2  = (const float*)d_in[7];
    const float* bhh2  = (const float*)d_in[8];
    const float* Wlin  = (const float*)d_in[9];
    const float* blin  = (const float*)d_in[10];
    float* out = (float*)d_out;

    cudaFuncSetAttribute(lstm_ws_kernel, cudaFuncAttributeMaxDynamicSharedMemorySize, SMEM_TOTAL);
    lstm_ws_kernel<<<128, 512, SMEM_TOTAL>>>(input, Wih1, Whh1, bih1, bhh1,
                                             Wih2, Whh2, bih2, bhh2, Wlin, blin, out);
}

// round 16
// speedup vs baseline: 1.0841x; 1.0162x over previous
#include <cuda_runtime.h>
#include <cuda_fp16.h>
#include <cstdint>
#include <cstddef>

#define NT 2048
#define RST 144

// ---- smem layout (bytes) ----
#define BUF0   0          // h1 slot 0: [64][72] half (rows 0-31 coh0, 32-63 coh1)
#define BUF1   9216       // h1 slot 1
#define A2H    18432      // h2 state
#define B1H    27648      // B tiles (fp16): 208*144 = 29952 each (shared by both cohorts)
#define B2AH   57600
#define B2BH   87552
#define O_WL   117504
#define O_PART 117760     // [64][8] float
#define SMEM_TOTAL 120832

__device__ __forceinline__ uint32_t s2u(const void* p){
    uint32_t a;
    asm("{ .reg .u64 t; cvta.to.shared.u64 t, %1; cvt.u32.u64 %0, t; }" : "=r"(a) : "l"(p));
    return a;
}
__device__ __forceinline__ void ldsm4(uint32_t* r, uint32_t a){
    asm volatile("ldmatrix.sync.aligned.m8n8.x4.shared.b16 {%0,%1,%2,%3}, [%4];"
        : "=r"(r[0]),"=r"(r[1]),"=r"(r[2]),"=r"(r[3]) : "r"(a));
}
__device__ __forceinline__ void mma16816(float* c, const uint32_t* a, uint32_t b0, uint32_t b1){
    asm volatile("mma.sync.aligned.m16n8k16.row.col.f32.f16.f16.f32 "
        "{%0,%1,%2,%3}, {%4,%5,%6,%7}, {%8,%9}, {%0,%1,%2,%3};"
        : "+f"(c[0]),"+f"(c[1]),"+f"(c[2]),"+f"(c[3])
        : "r"(a[0]),"r"(a[1]),"r"(a[2]),"r"(a[3]), "r"(b0),"r"(b1));
}
__device__ __forceinline__ void nbar_sync(int id, int cnt){
    asm volatile("bar.sync %0, %1;" :: "r"(id), "r"(cnt) : "memory");
}
// HW tanh unit: 1 MUFU op (plain PTX, sm_75+)
__device__ __forceinline__ float tanh_ap(float x){
    float r;
    asm("tanh.approx.f32 %0, %1;" : "=f"(r) : "f"(x));
    return r;
}
__device__ __forceinline__ float fast_sig(float x){
    return fmaf(0.5f, tanh_ap(0.5f * x), 0.5f);   // exact identity
}
__device__ __forceinline__ float fast_tanh(float x){
    return tanh_ap(x);
}
__device__ __forceinline__ float epi_update(const float* gc, float& c, int p){
    float r0 = __shfl_xor_sync(0xFFFFFFFFu, gc[0], 1);
    float r1 = __shfl_xor_sync(0xFFFFFFFFu, gc[1], 1);
    float r2 = __shfl_xor_sync(0xFFFFFFFFu, gc[2], 1);
    float r3 = __shfl_xor_sync(0xFFFFFFFFu, gc[3], 1);
    float gi = p ? r2 : gc[0];
    float gf = p ? r3 : gc[1];
    float gG = p ? gc[2] : r0;
    float gO = p ? gc[3] : r1;
    float cn = fast_sig(gf)*c + fast_sig(gi)*fast_tanh(gG);
    c = cn;
    return fast_sig(gO)*fast_tanh(cn);
}
// stage [204-row] weight block into [208][72] fp16 tile; cols [0,51)=W, 51=wx, 52=bias
__device__ void stageB(const float* W, const float* wx, const float* ba, const float* bb,
                       half* hi, int tid){
    for (int i = tid; i < 208*72; i += 512){
        int n = i / 72, k = i - n*72;
        float v = 0.0f;
        if (n < 204){
            int u = n >> 2, g = n & 3, row = g*51 + u;
            if (k < 51)                 v = W[row*51 + k];
            else if (k == 51 && wx)     v = wx[row];
            else if (k == 52 && ba)     v = ba[row] + bb[row];
        }
        hi[i] = __float2half(v);
    }
}

__global__ void __launch_bounds__(512, 1)
lstm_ws_kernel(const float* __restrict__ input,
               const float* __restrict__ Wih1, const float* __restrict__ Whh1,
               const float* __restrict__ bih1, const float* __restrict__ bhh1,
               const float* __restrict__ Wih2, const float* __restrict__ Whh2,
               const float* __restrict__ bih2, const float* __restrict__ bhh2,
               const float* __restrict__ Wlin, const float* __restrict__ blin,
               float* __restrict__ out)
{
    extern __shared__ char smem[];
    const int tid  = threadIdx.x;
    const int lane = tid & 31;
    const int wid  = tid >> 5;
    const int b0   = blockIdx.x * 64;
    const uint32_t sb = s2u(smem);

    half* buf[2] = { (half*)(smem + BUF0), (half*)(smem + BUF1) };
    half* a2h = (half*)(smem + A2H);

    // ---- init: stage weights, zero state ----
    stageB(Whh1, Wih1, bih1, bhh1, (half*)(smem + B1H),  tid);
    stageB(Wih2, 0,    bih2, bhh2, (half*)(smem + B2AH), tid);
    stageB(Whh2, 0,    0,    0,    (half*)(smem + B2BH), tid);
    for (int i = tid; i < 27648/4; i += 512) ((uint32_t*)(smem + BUF0))[i] = 0u;  // h1x2, h2
    for (int i = tid; i < 64*8; i += 512) ((float*)(smem + O_PART))[i] = 0.0f;
    if (tid < 52) ((float*)(smem + O_WL))[tid] = (tid < 51) ? Wlin[tid] : 0.0f;
    __syncthreads();
    if (tid < 64){
        buf[0][tid*72 + 51] = __float2half(input[(size_t)(b0 + tid)*NT]);  // x(0)
        buf[0][tid*72 + 52] = __float2half(1.0f);
        buf[1][tid*72 + 52] = __float2half(1.0f);
    }
    __syncthreads();

    // ---- cohort geometry: warps 0-7 -> cohort 0 (elems 0-31), 8-15 -> cohort 1 (32-63) ----
    const int coh = wid >> 3;
    const int cw  = wid & 7;           // warp within cohort: 0-2 = X, 3-7 = Y
    const int m0  = coh * 32;
    // named barriers: cohort0 uses {1,2}, cohort1 uses {3,4}
    const int B_REND = 1 + coh*2;      // X<->Y rendezvous (256 threads)
    const int B_IY   = 2 + coh*2;      // intra-Y (160 threads)

    const int g   = lane >> 2;
    const int tig = lane & 3;
    const int p   = tig & 1;
    const uint32_t aro  = (uint32_t)(((lane>>3)&1)*8*RST + (lane&7)*RST + ((lane>>4)&1)*16);
    const uint32_t bro4 = (uint32_t)((lane&7)*RST + ((lane>>3)&3)*16);
    const float* wlS = (const float*)(smem + O_WL);
    float* part = (float*)(smem + O_PART);

    const int er0 = m0 + p*8 + g, er1 = er0 + 16;
    const uint32_t ab[2][2] = {
        { sb + BUF0 + m0*RST + aro, sb + BUF0 + m0*RST + aro + 16*RST },
        { sb + BUF1 + m0*RST + aro, sb + BUF1 + m0*RST + aro + 16*RST } };

    if (cw < 3){
        // ================= X: layer-1 recurrence (3 warps per cohort) =================
        const int qx = cw;
        const int ns = qx * 9;
        const int nt = (qx == 2) ? 8 : 9;
        const uint32_t b1hb = sb + B1H + bro4;
        const int xe = m0 + lane;          // elem this thread loads x for (cw==0 only)

        float c1[2][9];
        #pragma unroll
        for (int j = 0; j < 9; j++){ c1[0][j] = 0.0f; c1[1][j] = 0.0f; }

        uint32_t fa[2][16];
        #pragma unroll
        for (int kc = 0; kc < 4; kc++){
            ldsm4(&fa[0][kc*4], ab[0][0] + kc*32);
            ldsm4(&fa[1][kc*4], ab[0][1] + kc*32);
        }

        #pragma unroll 1
        for (int t = 0; t < NT; t++){
            const int s = t & 1;
            float xv = 0.0f;
            if (cw == 0 && t + 1 < NT) xv = input[(size_t)(b0 + xe)*NT + t + 1];
            half* bh = buf[s];

            #pragma unroll
            for (int j = 0; j < 9; j++){
                if (j >= nt) break;
                const uint32_t nofs = (uint32_t)((ns + j)*8*RST);
                float g1a[4] = {0,0,0,0}, g1b[4] = {0,0,0,0};
                uint32_t b4[4];
                #pragma unroll
                for (int kc2 = 0; kc2 < 2; kc2++){
                    ldsm4(b4, b1hb + nofs + kc2*64);
                    mma16816(g1a, &fa[0][(2*kc2)*4],   b4[0], b4[1]);
                    mma16816(g1b, &fa[1][(2*kc2)*4],   b4[0], b4[1]);
                    mma16816(g1a, &fa[0][(2*kc2+1)*4], b4[2], b4[3]);
                    mma16816(g1b, &fa[1][(2*kc2+1)*4], b4[2], b4[3]);
                }
                float h0 = epi_update(g1a, c1[0][j], p);
                float h1 = epi_update(g1b, c1[1][j], p);
                int u = 2*(ns + j) + (tig >> 1);
                if (u < 51){
                    bh[er0*72 + u] = __float2half(h0);
                    bh[er1*72 + u] = __float2half(h1);
                }
            }
            if (cw == 0 && t + 1 < NT) bh[xe*72 + 51] = __float2half(xv);
            // single rendezvous: drains STS, publishes h1(t) to Y, and guarantees
            // Y has finished consuming slot s^1 (it arrived here after its prev step)
            nbar_sync(B_REND, 256);
            #pragma unroll
            for (int kc = 0; kc < 4; kc++){               // reload h1(t) for t+1
                ldsm4(&fa[0][kc*4], ab[s][0] + kc*32);
                ldsm4(&fa[1][kc*4], ab[s][1] + kc*32);
            }
        }
    } else {
        // ================= Y: layer-2 + output (5 warps per cohort) =================
        const int qy = cw - 3;             // 0..4
        const int nt = (qy == 0) ? 6 : 5;
        const int ns = (qy == 0) ? 0 : 6 + 5*(qy - 1);
        const uint32_t a2b0 = sb + A2H + m0*RST + aro, a2b1 = a2b0 + 16*RST;
        const uint32_t bahb = sb + B2AH + bro4;
        const uint32_t bbhb = sb + B2BH + bro4;
        const float blin0 = blin[0];
        const int oe = m0 + lane;          // out elem (cw==3 only)

        float c2[2][6], wlr[6];
        #pragma unroll
        for (int j = 0; j < 6; j++){
            c2[0][j] = 0.0f; c2[1][j] = 0.0f;
            wlr[j] = wlS[2*(ns + j) + (tig >> 1)];
        }
        uint32_t fa1[2][16], fa2[2][16];
        #pragma unroll
        for (int kc = 0; kc < 4; kc++){                   // h2(-1) = 0
            ldsm4(&fa2[0][kc*4], a2b0 + kc*32);
            ldsm4(&fa2[1][kc*4], a2b1 + kc*32);
        }

        #pragma unroll 1
        for (int t = 0; t < NT; t++){
            const int s = t & 1;
            nbar_sync(B_REND, 256);                       // h1(t) published by X
            #pragma unroll
            for (int kc = 0; kc < 4; kc++){
                ldsm4(&fa1[0][kc*4], ab[s][0] + kc*32);
                ldsm4(&fa1[1][kc*4], ab[s][1] + kc*32);
            }
            float pd0 = 0.0f, pd1 = 0.0f;
            #pragma unroll
            for (int j = 0; j < 6; j++){
                if (j >= nt) break;
                const uint32_t nofs = (uint32_t)((ns + j)*8*RST);
                float g2a[4] = {0,0,0,0}, g2b[4] = {0,0,0,0};
                uint32_t b4[4];
                #pragma unroll
                for (int kc2 = 0; kc2 < 2; kc2++){
                    ldsm4(b4, bahb + nofs + kc2*64);
                    mma16816(g2a, &fa1[0][(2*kc2)*4],   b4[0], b4[1]);
                    mma16816(g2b, &fa1[1][(2*kc2)*4],   b4[0], b4[1]);
                    mma16816(g2a, &fa1[0][(2*kc2+1)*4], b4[2], b4[3]);
                    mma16816(g2b, &fa1[1][(2*kc2+1)*4], b4[2], b4[3]);
                }
                #pragma unroll
                for (int kc2 = 0; kc2 < 2; kc2++){
                    ldsm4(b4, bbhb + nofs + kc2*64);
                    mma16816(g2a, &fa2[0][(2*kc2)*4],   b4[0], b4[1]);
                    mma16816(g2b, &fa2[1][(2*kc2)*4],   b4[0], b4[1]);
                    mma16816(g2a, &fa2[0][(2*kc2+1)*4], b4[2], b4[3]);
                    mma16816(g2b, &fa2[1][(2*kc2+1)*4], b4[2], b4[3]);
                }
                float h0 = epi_update(g2a, c2[0][j], p);
                float h1 = epi_update(g2b, c2[1][j], p);
                int u = 2*(ns + j) + (tig >> 1);
                if (u < 51){
                    a2h[er0*72 + u] = __float2half(h0);
                    a2h[er1*72 + u] = __float2half(h1);
                }
                pd0 = fmaf(h0, wlr[j], pd0);
                pd1 = fmaf(h1, wlr[j], pd1);
            }
            pd0 += __shfl_xor_sync(0xFFFFFFFFu, pd0, 2);
            pd1 += __shfl_xor_sync(0xFFFFFFFFu, pd1, 2);
            if (tig < 2){
                part[er0*8 + qy] = pd0;
                part[er1*8 + qy] = pd1;
            }
            nbar_sync(B_IY, 160);                         // h2(t) + part visible in Y
            if (cw == 3){
                const float* pr = part + oe*8;
                out[(size_t)(b0 + oe)*NT + t] =
                    (pr[0] + pr[1]) + (pr[2] + pr[3]) + pr[4] + blin0;
            }
            #pragma unroll
            for (int kc = 0; kc < 4; kc++){               // reload h2(t); next writes are
                ldsm4(&fa2[0][kc*4], a2b0 + kc*32);       // ordered behind next rendezvous
                ldsm4(&fa2[1][kc*4], a2b1 + kc*32);
            }
        }
    }
}

extern "C" void kernel_launch(void* const* d_in, const int* in_sizes, int n_in,
                              void* d_out, int out_size)
{
    (void)in_sizes; (void)n_in; (void)out_size;
    const float* input = (const float*)d_in[0];
    const float* Wih1  = (const float*)d_in[1];
    const float* Whh1  = (const float*)d_in[2];
    const float* bih1  = (const float*)d_in[3];
    const float* bhh1  = (const float*)d_in[4];
    const float* Wih2  = (const float*)d_in[5];
    const float* Whh2  = (const float*)d_in[6];
    const float* bih2  = (const float*)d_in[7];
    const float* bhh2  = (const float*)d_in[8];
    const float* Wlin  = (const float*)d_in[9];
    const float* blin  = (const float*)d_in[10];
    float* out = (float*)d_out;

    cudaFuncSetAttribute(lstm_ws_kernel, cudaFuncAttributeMaxDynamicSharedMemorySize, SMEM_TOTAL);
    lstm_ws_kernel<<<128, 512, SMEM_TOTAL>>>(input, Wih1, Whh1, bih1, bhh1,
                                             Wih2, Whh2, bih2, bhh2, Wlin, blin, out);
}

// round 17
// speedup vs baseline: 1.0935x; 1.0086x over previous
#include <cuda_runtime.h>
#include <cuda_fp16.h>
#include <cstdint>
#include <cstddef>

#define NT 2048
#define RSTN 240          // A/B row stride bytes (120 halves; 15*16B -> bank-safe)
#define RH 120            // halves per row

// ---- smem layout (bytes) ----
// A slots: [64][120] half; cols 0-50 h1, 51 x, 52 one, 53-103 h2, 104+ pad
#define BUF0   0
#define BUF1   15360
#define B1H    30720      // B1: [208][120] half (cols>=53 zero)
#define B2H    80640      // B2 merged: Wih2 | 0 | b2 | Whh2 | 0
#define O_WL   130560
#define O_PART 130816     // [64][8] float
#define SMEM_TOTAL 132864

__device__ __forceinline__ uint32_t s2u(const void* p){
    uint32_t a;
    asm("{ .reg .u64 t; cvta.to.shared.u64 t, %1; cvt.u32.u64 %0, t; }" : "=r"(a) : "l"(p));
    return a;
}
__device__ __forceinline__ void ldsm4(uint32_t* r, uint32_t a){
    asm volatile("ldmatrix.sync.aligned.m8n8.x4.shared.b16 {%0,%1,%2,%3}, [%4];"
        : "=r"(r[0]),"=r"(r[1]),"=r"(r[2]),"=r"(r[3]) : "r"(a));
}
__device__ __forceinline__ void ldsm2(uint32_t* r, uint32_t a){
    asm volatile("ldmatrix.sync.aligned.m8n8.x2.shared.b16 {%0,%1}, [%2];"
        : "=r"(r[0]),"=r"(r[1]) : "r"(a));
}
__device__ __forceinline__ void mma16816(float* c, const uint32_t* a, uint32_t b0, uint32_t b1){
    asm volatile("mma.sync.aligned.m16n8k16.row.col.f32.f16.f16.f32 "
        "{%0,%1,%2,%3}, {%4,%5,%6,%7}, {%8,%9}, {%0,%1,%2,%3};"
        : "+f"(c[0]),"+f"(c[1]),"+f"(c[2]),"+f"(c[3])
        : "r"(a[0]),"r"(a[1]),"r"(a[2]),"r"(a[3]), "r"(b0),"r"(b1));
}
__device__ __forceinline__ void nbar_sync(int id, int cnt){
    asm volatile("bar.sync %0, %1;" :: "r"(id), "r"(cnt) : "memory");
}
__device__ __forceinline__ float tanh_ap(float x){
    float r;
    asm("tanh.approx.f32 %0, %1;" : "=f"(r) : "f"(x));
    return r;
}
__device__ __forceinline__ float fast_sig(float x){
    return fmaf(0.5f, tanh_ap(0.5f * x), 0.5f);
}
__device__ __forceinline__ float epi_update(const float* gc, float& c, int p){
    float r0 = __shfl_xor_sync(0xFFFFFFFFu, gc[0], 1);
    float r1 = __shfl_xor_sync(0xFFFFFFFFu, gc[1], 1);
    float r2 = __shfl_xor_sync(0xFFFFFFFFu, gc[2], 1);
    float r3 = __shfl_xor_sync(0xFFFFFFFFu, gc[3], 1);
    float gi = p ? r2 : gc[0];
    float gf = p ? r3 : gc[1];
    float gG = p ? gc[2] : r0;
    float gO = p ? gc[3] : r1;
    float cn = fast_sig(gf)*c + fast_sig(gi)*tanh_ap(gG);
    c = cn;
    return fast_sig(gO)*tanh_ap(cn);
}
// stage B1: rows n=4u+g; cols 0-50 Whh1, 51 Wih1, 52 b1, else 0
__device__ void stageB1(const float* Whh1, const float* Wih1,
                        const float* bih1, const float* bhh1, half* D, int tid){
    for (int i = tid; i < 208*RH; i += 512){
        int n = i / RH, k = i - n*RH;
        float v = 0.0f;
        if (n < 204){
            int u = n >> 2, g = n & 3, row = g*51 + u;
            if (k < 51)        v = Whh1[row*51 + k];
            else if (k == 51)  v = Wih1[row];
            else if (k == 52)  v = bih1[row] + bhh1[row];
        }
        D[i] = __float2half(v);
    }
}
// stage B2 merged: cols 0-50 Wih2, 51 0, 52 b2, 53-103 Whh2, else 0
__device__ void stageB2(const float* Wih2, const float* Whh2,
                        const float* bih2, const float* bhh2, half* D, int tid){
    for (int i = tid; i < 208*RH; i += 512){
        int n = i / RH, k = i - n*RH;
        float v = 0.0f;
        if (n < 204){
            int u = n >> 2, g = n & 3, row = g*51 + u;
            if (k < 51)                   v = Wih2[row*51 + k];
            else if (k == 52)             v = bih2[row] + bhh2[row];
            else if (k >= 53 && k < 104)  v = Whh2[row*51 + (k - 53)];
        }
        D[i] = __float2half(v);
    }
}

__global__ void __launch_bounds__(512, 1)
lstm_ws_kernel(const float* __restrict__ input,
               const float* __restrict__ Wih1, const float* __restrict__ Whh1,
               const float* __restrict__ bih1, const float* __restrict__ bhh1,
               const float* __restrict__ Wih2, const float* __restrict__ Whh2,
               const float* __restrict__ bih2, const float* __restrict__ bhh2,
               const float* __restrict__ Wlin, const float* __restrict__ blin,
               float* __restrict__ out)
{
    extern __shared__ char smem[];
    const int tid  = threadIdx.x;
    const int lane = tid & 31;
    const int wid  = tid >> 5;
    const int b0   = blockIdx.x * 64;
    const uint32_t sb = s2u(smem);

    half* buf[2] = { (half*)(smem + BUF0), (half*)(smem + BUF1) };

    // ---- init: stage weights, zero A slots ----
    stageB1(Whh1, Wih1, bih1, bhh1, (half*)(smem + B1H), tid);
    stageB2(Wih2, Whh2, bih2, bhh2, (half*)(smem + B2H), tid);
    for (int i = tid; i < 30720/4; i += 512) ((uint32_t*)(smem + BUF0))[i] = 0u;
    for (int i = tid; i < 64*8; i += 512) ((float*)(smem + O_PART))[i] = 0.0f;
    if (tid < 52) ((float*)(smem + O_WL))[tid] = (tid < 51) ? Wlin[tid] : 0.0f;
    __syncthreads();
    if (tid < 64){
        buf[0][tid*RH + 51] = __float2half(input[(size_t)(b0 + tid)*NT]);  // x(0)
        buf[0][tid*RH + 52] = __float2half(1.0f);
        buf[1][tid*RH + 52] = __float2half(1.0f);
    }
    __syncthreads();

    // ---- cohorts: warps 0-7 -> elems 0-31, 8-15 -> elems 32-63 ----
    const int coh = wid >> 3;
    const int cw  = wid & 7;           // 0-2 = X (layer1), 3-7 = Y (layer2+out)
    const int m0  = coh * 32;
    const int B_REND = 1 + coh*2;
    const int B_IY   = 2 + coh*2;

    const int g   = lane >> 2;
    const int tig = lane & 3;
    const int p   = tig & 1;
    const uint32_t aro  = (uint32_t)(((lane>>3)&1)*8*RSTN + (lane&7)*RSTN + ((lane>>4)&1)*16);
    const uint32_t bro4 = (uint32_t)((lane&7)*RSTN + ((lane>>3)&3)*16);
    const uint32_t bro2 = (uint32_t)((lane&7)*RSTN + ((lane>>3)&1)*16);
    const float* wlS = (const float*)(smem + O_WL);
    float* part = (float*)(smem + O_PART);

    const int er0 = m0 + p*8 + g, er1 = er0 + 16;
    const uint32_t ab[2][2] = {
        { sb + BUF0 + m0*RSTN + aro, sb + BUF0 + m0*RSTN + aro + 16*RSTN },
        { sb + BUF1 + m0*RSTN + aro, sb + BUF1 + m0*RSTN + aro + 16*RSTN } };

    if (cw < 3){
        // ================= X: layer-1 recurrence (chunks 0-3) =================
        const int qx = cw;
        const int ns = qx * 9;
        const int nt = (qx == 2) ? 8 : 9;
        const uint32_t b1hb = sb + B1H + bro4;
        const int xe = m0 + lane;

        float c1[2][9];
        #pragma unroll
        for (int j = 0; j < 9; j++){ c1[0][j] = 0.0f; c1[1][j] = 0.0f; }

        uint32_t fa[2][16];
        #pragma unroll
        for (int kc = 0; kc < 4; kc++){
            ldsm4(&fa[0][kc*4], ab[0][0] + kc*32);
            ldsm4(&fa[1][kc*4], ab[0][1] + kc*32);
        }

        #pragma unroll 1
        for (int t = 0; t < NT; t++){
            const int s = t & 1;
            float xv = 0.0f;
            if (cw == 0 && t + 1 < NT) xv = input[(size_t)(b0 + xe)*NT + t + 1];
            half* bh = buf[s];

            #pragma unroll
            for (int j = 0; j < 9; j++){
                if (j >= nt) break;
                const uint32_t nofs = (uint32_t)((ns + j)*8*RSTN);
                float g1a[4] = {0,0,0,0}, g1b[4] = {0,0,0,0};
                uint32_t b4[4];
                #pragma unroll
                for (int kc2 = 0; kc2 < 2; kc2++){
                    ldsm4(b4, b1hb + nofs + kc2*64);
                    mma16816(g1a, &fa[0][(2*kc2)*4],   b4[0], b4[1]);
                    mma16816(g1b, &fa[1][(2*kc2)*4],   b4[0], b4[1]);
                    mma16816(g1a, &fa[0][(2*kc2+1)*4], b4[2], b4[3]);
                    mma16816(g1b, &fa[1][(2*kc2+1)*4], b4[2], b4[3]);
                }
                float h0 = epi_update(g1a, c1[0][j], p);
                float h1 = epi_update(g1b, c1[1][j], p);
                int u = 2*(ns + j) + (tig >> 1);
                if (u < 51){
                    bh[er0*RH + u] = __float2half(h0);
                    bh[er1*RH + u] = __float2half(h1);
                }
            }
            if (cw == 0 && t + 1 < NT) bh[xe*RH + 51] = __float2half(xv);
            nbar_sync(B_REND, 256);       // publish h1(t)/x(t+1); slot swap safe
            #pragma unroll
            for (int kc = 0; kc < 4; kc++){
                ldsm4(&fa[0][kc*4], ab[s][0] + kc*32);
                ldsm4(&fa[1][kc*4], ab[s][1] + kc*32);
            }
        }
    } else {
        // ================= Y: merged layer-2 GEMM (chunks 0-6) + out =================
        const int qy = cw - 3;             // 0..4
        const int nt = (qy == 0) ? 6 : 5;
        const int ns = (qy == 0) ? 0 : 6 + 5*(qy - 1);
        const uint32_t b2b4 = sb + B2H + bro4;
        const uint32_t b2b2 = sb + B2H + bro2 + 192;   // chunk 6
        const float blin0 = blin[0];
        const int oe = m0 + lane;          // out elem (cw==7 only)

        float c2[2][6], wlr[6];
        #pragma unroll
        for (int j = 0; j < 6; j++){
            c2[0][j] = 0.0f; c2[1][j] = 0.0f;
            wlr[j] = wlS[2*(ns + j) + (tig >> 1)];
        }

        #pragma unroll 1
        for (int t = 0; t < NT; t++){
            const int s = t & 1;
            half* hw = buf[s ^ 1];                     // h2(t) target slot
            nbar_sync(B_REND, 256);                    // h1(t)+h2(t-1) in slot s
            uint32_t fa[2][28];
            #pragma unroll
            for (int kc = 0; kc < 7; kc++){
                ldsm4(&fa[0][kc*4], ab[s][0] + kc*32);
                ldsm4(&fa[1][kc*4], ab[s][1] + kc*32);
            }
            float pd0 = 0.0f, pd1 = 0.0f;
            #pragma unroll
            for (int j = 0; j < 6; j++){
                if (j >= nt) break;
                const uint32_t nofs = (uint32_t)((ns + j)*8*RSTN);
                float g2a[4] = {0,0,0,0}, g2b[4] = {0,0,0,0};
                uint32_t b01[4], b23[4], b45[4], b6[2];
                ldsm4(b01, b2b4 + nofs);
                ldsm4(b23, b2b4 + nofs + 64);
                ldsm4(b45, b2b4 + nofs + 128);
                ldsm2(b6,  b2b2 + nofs);
                mma16816(g2a, &fa[0][0],  b01[0], b01[1]);
                mma16816(g2b, &fa[1][0],  b01[0], b01[1]);
                mma16816(g2a, &fa[0][4],  b01[2], b01[3]);
                mma16816(g2b, &fa[1][4],  b01[2], b01[3]);
                mma16816(g2a, &fa[0][8],  b23[0], b23[1]);
                mma16816(g2b, &fa[1][8],  b23[0], b23[1]);
                mma16816(g2a, &fa[0][12], b23[2], b23[3]);
                mma16816(g2b, &fa[1][12], b23[2], b23[3]);
                mma16816(g2a, &fa[0][16], b45[0], b45[1]);
                mma16816(g2b, &fa[1][16], b45[0], b45[1]);
                mma16816(g2a, &fa[0][20], b45[2], b45[3]);
                mma16816(g2b, &fa[1][20], b45[2], b45[3]);
                mma16816(g2a, &fa[0][24], b6[0],  b6[1]);
                mma16816(g2b, &fa[1][24], b6[0],  b6[1]);
                float h0 = epi_update(g2a, c2[0][j], p);
                float h1 = epi_update(g2b, c2[1][j], p);
                int u = 2*(ns + j) + (tig >> 1);
                if (u < 51){
                    hw[er0*RH + 53 + u] = __float2half(h0);
                    hw[er1*RH + 53 + u] = __float2half(h1);
                }
                pd0 = fmaf(h0, wlr[j], pd0);
                pd1 = fmaf(h1, wlr[j], pd1);
            }
            pd0 += __shfl_xor_sync(0xFFFFFFFFu, pd0, 2);
            pd1 += __shfl_xor_sync(0xFFFFFFFFu, pd1, 2);
            if (tig < 2){
                part[er0*8 + qy] = pd0;
                part[er1*8 + qy] = pd1;
            }
            nbar_sync(B_IY, 160);                      // part visible in Y
            if (cw == 7){                              // lightest warp writes out
                const float* pr = part + oe*8;
                out[(size_t)(b0 + oe)*NT + t] =
                    (pr[0] + pr[1]) + (pr[2] + pr[3]) + pr[4] + blin0;
            }
        }
    }
}

extern "C" void kernel_launch(void* const* d_in, const int* in_sizes, int n_in,
                              void* d_out, int out_size)
{
    (void)in_sizes; (void)n_in; (void)out_size;
    const float* input = (const float*)d_in[0];
    const float* Wih1  = (const float*)d_in[1];
    const float* Whh1  = (const float*)d_in[2];
    const float* bih1  = (const float*)d_in[3];
    const float* bhh1  = (const float*)d_in[4];
    const float* Wih2  = (const float*)d_in[5];
    const float* Whh2  = (const float*)d_in[6];
    const float* bih2  = (const float*)d_in[7];
    const float* bhh2  = (const float*)d_in[8];
    const float* Wlin  = (const float*)d_in[9];
    const float* blin  = (const float*)d_in[10];
    float* out = (float*)d_out;

    cudaFuncSetAttribute(lstm_ws_kernel, cudaFuncAttributeMaxDynamicSharedMemorySize, SMEM_TOTAL);
    lstm_ws_kernel<<<128, 512, SMEM_TOTAL>>>(input, Wih1, Whh1, bih1, bhh1,
                                             Wih2, Whh2, bih2, bhh2, Wlin, blin, out);
}